// round 16
// baseline (speedup 1.0000x reference)
#include <cuda_runtime.h>
#include <cuda_fp16.h>
#include <cstdint>

// Problem dims (fixed by the dataset)
#define BB 4096   // batch
#define DD 1024   // model dim
#define EE 8      // experts
#define CC 4096   // expert output dim
#define KSEL 4    // top-k

// Main GEMM tiling
#define BM 128
#define BN 128
#define BK 64
#define NCH 16            // 16 k-chunks; each carries A_h, A_l, B
#define NSTG 2            // double buffer
#define ASTR 72           // A smem row stride (elems): 144B -> conflict-free ldmatrix
#define BSTR 136          // B smem row stride (elems): 272B -> conflict-free ldmatrix
#define A_T_B (BM * ASTR * 2)            // 18432 per A tile
#define B_T_B (BK * BSTR * 2)            // 17408 per B tile
#define STAGE_B (2 * A_T_B + B_T_B)      // 54272
#define SMEM_DYN (NSTG * STAGE_B)        // 108544
// offsets within a stage
#define OFF_AH 0
#define OFF_AL A_T_B
#define OFF_B  (2 * A_T_B)
#define MAXT 136                          // max M-tiles

// ---------------------------------------------------------------------------
// Static device scratch (allocation-free rule)
// ---------------------------------------------------------------------------
__device__ float g_gates[BB * EE];
__device__ int   g_cnt[EE];
__device__ int   g_list[EE * BB];          // per-expert row lists (padded with -1)
__device__ int4  g_rowslot[BB];            // per row: 4x ((e<<16)|slot)
__device__ int   g_map_e[MAXT];
__device__ int   g_map_lb[MAXT];           // list-index base for tile
__device__ int   g_pbase[EE];              // padded global slot base per expert
__device__ __align__(16) __half g_x_h[BB * DD];
__device__ __align__(16) __half g_x_l[BB * DD];
__device__ __align__(16) __half g_w[(size_t)EE * DD * CC];
__device__ __align__(16) float g_eo[(size_t)MAXT * BM * CC];  // per-(slot,col) contrib

__device__ __forceinline__ uint32_t smem_u32(const void* p) {
    uint32_t a;
    asm("{ .reg .u64 t; cvta.to.shared.u64 t, %1; cvt.u32.u64 %0, t; }"
        : "=r"(a) : "l"(p));
    return a;
}

// ---------------------------------------------------------------------------
// Kernel 0: zero counters
// ---------------------------------------------------------------------------
__global__ void zero_cnt() { if (threadIdx.x < EE) g_cnt[threadIdx.x] = 0; }

// ---------------------------------------------------------------------------
// Kernel 1: gating. One warp per row; float4 loads, deep MLP.
// ---------------------------------------------------------------------------
__global__ void gating_kernel(const float* __restrict__ x,
                              const float* __restrict__ wg) {
    int row  = (blockIdx.x * blockDim.x + threadIdx.x) >> 5;
    int lane = threadIdx.x & 31;
    if (row >= BB) return;

    const float* xr = x + (size_t)row * DD;
    float acc[EE];
#pragma unroll
    for (int e = 0; e < EE; e++) acc[e] = 0.f;

    // lane handles j = lane*4 + 128*i, 4 consecutive elements via float4
#pragma unroll
    for (int i = 0; i < 8; i++) {
        int j0 = lane * 4 + i * 128;
        float4 xv = *(const float4*)(xr + j0);
        float xq[4] = {xv.x, xv.y, xv.z, xv.w};
#pragma unroll
        for (int q = 0; q < 4; q++) {
            const float4* wr = (const float4*)(wg + (size_t)(j0 + q) * EE);
            float4 w0 = wr[0], w1 = wr[1];
            acc[0] += xq[q] * w0.x; acc[1] += xq[q] * w0.y;
            acc[2] += xq[q] * w0.z; acc[3] += xq[q] * w0.w;
            acc[4] += xq[q] * w1.x; acc[5] += xq[q] * w1.y;
            acc[6] += xq[q] * w1.z; acc[7] += xq[q] * w1.w;
        }
    }
#pragma unroll
    for (int off = 16; off; off >>= 1)
#pragma unroll
        for (int e = 0; e < EE; e++)
            acc[e] += __shfl_xor_sync(0xffffffffu, acc[e], off);

    if (lane == 0) {
        unsigned used = 0;
        float sl[KSEL]; int si[KSEL];
#pragma unroll
        for (int t = 0; t < KSEL; t++) {
            float best = -3.0e38f; int bi = 0;
#pragma unroll
            for (int e = 0; e < EE; e++) {
                bool ok = !((used >> e) & 1u);
                if (ok && acc[e] > best) { best = acc[e]; bi = e; }
            }
            used |= 1u << bi; sl[t] = best; si[t] = bi;
        }
        float m = sl[0], ex[KSEL], s = 0.f;
#pragma unroll
        for (int t = 0; t < KSEL; t++) { ex[t] = expf(sl[t] - m); s += ex[t]; }
        float inv = 1.f / s;
        float out[EE];
#pragma unroll
        for (int e = 0; e < EE; e++) out[e] = 0.f;
#pragma unroll
        for (int t = 0; t < KSEL; t++) out[si[t]] = ex[t] * inv;
#pragma unroll
        for (int e = 0; e < EE; e++) g_gates[(size_t)row * EE + e] = out[e];

        int pk[KSEL];
#pragma unroll
        for (int t = 0; t < KSEL; t++) {
            int slot = atomicAdd(&g_cnt[si[t]], 1);
            g_list[si[t] * BB + slot] = row;
            pk[t] = (si[t] << 16) | slot;
        }
        g_rowslot[row] = make_int4(pk[0], pk[1], pk[2], pk[3]);
    }
}

// ---------------------------------------------------------------------------
// Kernel 2: build tile map (serial, trivial work)
// ---------------------------------------------------------------------------
__global__ void map_kernel() {
    if (threadIdx.x != 0 || blockIdx.x != 0) return;
    int t = 0;
    for (int e = 0; e < EE; e++) {
        int c  = g_cnt[e];
        int nt = (c + BM - 1) >> 7;
        g_pbase[e] = t * BM;
        for (int i = 0; i < nt; i++) {
            g_map_e[t]  = e;
            g_map_lb[t] = e * BB + i * BM;
            t++;
        }
        for (int s = c; s < nt * BM; s++) g_list[e * BB + s] = -1;
    }
    for (; t < MAXT; t++) g_map_e[t] = -1;
}

// ---------------------------------------------------------------------------
// Kernel 3: split x into hi/lo fp16 (x = h + l, ~21-bit effective mantissa)
// ---------------------------------------------------------------------------
__global__ void convert_x(const float* __restrict__ x) {
    int i = blockIdx.x * blockDim.x + threadIdx.x;
    float4 v = ((const float4*)x)[i];
    __half h0 = __float2half(v.x), h1 = __float2half(v.y);
    __half h2 = __float2half(v.z), h3 = __float2half(v.w);
    __half2* hp = (__half2*)g_x_h;
    __half2* lp = (__half2*)g_x_l;
    hp[2 * i]     = __halves2half2(h0, h1);
    hp[2 * i + 1] = __halves2half2(h2, h3);
    lp[2 * i]     = __halves2half2(
        __float2half(v.x - __half2float(h0)),
        __float2half(v.y - __half2float(h1)));
    lp[2 * i + 1] = __halves2half2(
        __float2half(v.z - __half2float(h2)),
        __float2half(v.w - __half2float(h3)));
}

// ---------------------------------------------------------------------------
// Kernel 4: w -> single fp16 copy
// ---------------------------------------------------------------------------
__global__ void convert_w(const float* __restrict__ w) {
    size_t i = (size_t)blockIdx.x * blockDim.x + threadIdx.x;
    float4 v = ((const float4*)w)[i];
    __half2* hp = (__half2*)g_w;
    hp[2 * i]     = __halves2half2(__float2half(v.x), __float2half(v.y));
    hp[2 * i + 1] = __halves2half2(__float2half(v.z), __float2half(v.w));
}

// ---------------------------------------------------------------------------
// Kernel 5: sparse expert GEMM, fp16 two-term split, wide-N, BK=64,
// fragment-software-pipelined: AH double-buffered (prefetch next ks during
// pass-l), AL hoisted before pass-h. 256 threads, 8 warps 4(M)x2(N),
// double buffer, 1 barrier/chunk, 2 CTAs/SM. grid = (136, 32).
// ---------------------------------------------------------------------------
__global__ __launch_bounds__(256, 2)
void moe_main(const float* __restrict__ be) {
    const int t = blockIdx.x;
    const int e = g_map_e[t];
    if (e < 0) return;
    const int nb = blockIdx.y;

    extern __shared__ __align__(128) char sdyn[];
    __shared__ int   rl[BM];
    __shared__ float Gs[BM];
    __shared__ float Es[BN];

    const int tid   = threadIdx.x;
    const int lane  = tid & 31;
    const int wid   = tid >> 5;
    const int warpM = wid >> 1;          // 0..3 (32 rows each)
    const int warpN = wid & 1;           // 0..1 (64 cols each)

    if (tid < BM) {
        int r = g_list[g_map_lb[t] + tid];
        rl[tid] = (r < 0) ? 0 : r;
        Gs[tid] = (r < 0) ? 0.f : g_gates[(size_t)r * EE + e];
    } else if (tid < BM + BN) {
        Es[tid - BM] = be[(size_t)e * CC + nb * BN + (tid - BM)];
    }
    __syncthreads();

    const uint32_t sb = smem_u32(sdyn);

    // A loader: 128 rows x 64 elems = 1024 x 16B chunks; 4 per thread
    size_t rowoffA[4];
#pragma unroll
    for (int i = 0; i < 4; i++)
        rowoffA[i] = (size_t)rl[(tid + 256 * i) >> 3] * DD + ((tid & 7) * 8);
    uint32_t dstA[4];
#pragma unroll
    for (int i = 0; i < 4; i++)
        dstA[i] = (uint32_t)((((tid + 256 * i) >> 3) * ASTR + (tid & 7) * 8) * 2);
    // B loader: 64 rows x 128 elems = 1024 x 16B chunks; 4 per thread
    const int b_row0 = tid >> 4;             // +16 per i
    const int b_ch   = (tid & 15) * 8;
    uint32_t dstB[4];
#pragma unroll
    for (int i = 0; i < 4; i++)
        dstB[i] = (uint32_t)(((b_row0 + 16 * i) * BSTR + b_ch) * 2);

    const __half* wptr = g_w + (size_t)e * DD * CC;

    auto issue = [&](int kc) {
        int kk = kc * BK;
        uint32_t st = sb + (uint32_t)(kc & 1) * STAGE_B;
#pragma unroll
        for (int i = 0; i < 4; i++) {
            const void* s0 = g_x_h + rowoffA[i] + kk;
            asm volatile("cp.async.cg.shared.global [%0], [%1], 16;"
                         :: "r"(st + OFF_AH + dstA[i]), "l"(s0));
            const void* s1 = g_x_l + rowoffA[i] + kk;
            asm volatile("cp.async.cg.shared.global [%0], [%1], 16;"
                         :: "r"(st + OFF_AL + dstA[i]), "l"(s1));
        }
#pragma unroll
        for (int i = 0; i < 4; i++) {
            const void* s0 = wptr + (size_t)(kk + b_row0 + 16 * i) * CC
                             + nb * BN + b_ch;
            asm volatile("cp.async.cg.shared.global [%0], [%1], 16;"
                         :: "r"(st + OFF_B + dstB[i]), "l"(s0));
        }
        asm volatile("cp.async.commit_group;");
    };

    float acc[2][8][4];
#pragma unroll
    for (int mf = 0; mf < 2; mf++)
#pragma unroll
        for (int nf = 0; nf < 8; nf++)
#pragma unroll
            for (int q = 0; q < 4; q++) acc[mf][nf][q] = 0.f;

    const int lm_row = lane & 15;
    const int lm_col = (lane >> 4) << 3;

    // fragment loaders (ks-parameterized)
    auto loadA = [&](uint32_t st, uint32_t off, int ks, uint32_t (&dst)[2][4]) {
#pragma unroll
        for (int mf = 0; mf < 2; mf++) {
            uint32_t addr = st + off +
                (uint32_t)(((warpM * 32 + mf * 16 + lm_row) * ASTR +
                            ks * 16 + lm_col) * 2);
            asm volatile(
                "ldmatrix.sync.aligned.m8n8.x4.shared.b16 {%0,%1,%2,%3}, [%4];"
                : "=r"(dst[mf][0]), "=r"(dst[mf][1]),
                  "=r"(dst[mf][2]), "=r"(dst[mf][3])
                : "r"(addr));
        }
    };
    auto loadB = [&](uint32_t st, int ks, uint32_t (&b)[8][2]) {
#pragma unroll
        for (int np = 0; np < 4; np++) {
            uint32_t addr = st + OFF_B +
                (uint32_t)(((ks * 16 + lm_row) * BSTR +
                            warpN * 64 + np * 16 + lm_col) * 2);
            uint32_t t0, t1, t2, t3;
            asm volatile(
                "ldmatrix.sync.aligned.m8n8.x4.trans.shared.b16 {%0,%1,%2,%3}, [%4];"
                : "=r"(t0), "=r"(t1), "=r"(t2), "=r"(t3) : "r"(addr));
            b[np * 2][0] = t0;     b[np * 2][1] = t1;
            b[np * 2 + 1][0] = t2; b[np * 2 + 1][1] = t3;
        }
    };
    auto mma_all = [&](uint32_t (&a)[2][4], uint32_t (&b)[8][2]) {
#pragma unroll
        for (int mf = 0; mf < 2; mf++)
#pragma unroll
            for (int nf = 0; nf < 8; nf++)
                asm volatile(
                    "mma.sync.aligned.m16n8k16.row.col.f32.f16.f16.f32 "
                    "{%0,%1,%2,%3}, {%4,%5,%6,%7}, {%8,%9}, {%0,%1,%2,%3};"
                    : "+f"(acc[mf][nf][0]), "+f"(acc[mf][nf][1]),
                      "+f"(acc[mf][nf][2]), "+f"(acc[mf][nf][3])
                    : "r"(a[mf][0]), "r"(a[mf][1]),
                      "r"(a[mf][2]), "r"(a[mf][3]),
                      "r"(b[nf][0]), "r"(b[nf][1]));
    };

    issue(0);

    for (int c = 0; c < NCH; c++) {
        asm volatile("cp.async.wait_group 0;" ::: "memory");
        __syncthreads();
        if (c + 1 < NCH) issue(c + 1);

        uint32_t st = sb + (uint32_t)(c & 1) * STAGE_B;
        uint32_t ah[2][2][4], al[2][4], b[8][2];

        loadA(st, OFF_AH, 0, ah[0]);       // prologue: AH(0)
#pragma unroll
        for (int ks = 0; ks < 4; ks++) {
            loadB(st, ks, b);              // B for this ks
            loadA(st, OFF_AL, ks, al);     // AL early (consumed 16 MMAs later)
            mma_all(ah[ks & 1], b);        // pass h
            if (ks < 3)
                loadA(st, OFF_AH, ks + 1, ah[(ks + 1) & 1]);  // prefetch next AH
            mma_all(al, b);                // pass l
        }
    }

    // epilogue: g_eo[t*BM + local_row][nb*BN + col] = g * exp(acc + bias)
    const int r0 = warpM * 32 + (lane >> 2);
    const int c0 = warpN * 64 + (lane & 3) * 2;
    float* ob = g_eo + ((size_t)t * BM) * CC + (size_t)nb * BN;
#pragma unroll
    for (int mf = 0; mf < 2; mf++)
#pragma unroll
        for (int q = 0; q < 2; q++) {
            int rr = r0 + mf * 16 + q * 8;
            float g = Gs[rr];
#pragma unroll
            for (int nf = 0; nf < 8; nf++) {
                int cc = c0 + nf * 8;
                float v0 = g * __expf(acc[mf][nf][q * 2 + 0] + Es[cc]);
                float v1 = g * __expf(acc[mf][nf][q * 2 + 1] + Es[cc + 1]);
                *(float2*)(ob + (size_t)rr * CC + cc) = make_float2(v0, v1);
            }
        }
}

// ---------------------------------------------------------------------------
// Kernel 6: final combine. Each block = one row; sum the row's 4 fixed-order
// expert contributions (coalesced streams), eps guard, log.
// ---------------------------------------------------------------------------
__global__ void final_kernel(float* __restrict__ y) {
    int row = blockIdx.x;
    int4 rs = g_rowslot[row];
    const float* p0 = g_eo + (size_t)(g_pbase[rs.x >> 16] + (rs.x & 0xFFFF)) * CC;
    const float* p1 = g_eo + (size_t)(g_pbase[rs.y >> 16] + (rs.y & 0xFFFF)) * CC;
    const float* p2 = g_eo + (size_t)(g_pbase[rs.z >> 16] + (rs.z & 0xFFFF)) * CC;
    const float* p3 = g_eo + (size_t)(g_pbase[rs.w >> 16] + (rs.w & 0xFFFF)) * CC;
    float4* yo = (float4*)(y + (size_t)row * CC);
#pragma unroll
    for (int i = 0; i < 4; i++) {
        int c = threadIdx.x + i * 256;
        float4 a = ((const float4*)p0)[c];
        float4 b = ((const float4*)p1)[c];
        float4 d = ((const float4*)p2)[c];
        float4 f = ((const float4*)p3)[c];
        float s0 = a.x + b.x + d.x + f.x;
        float s1 = a.y + b.y + d.y + f.y;
        float s2 = a.z + b.z + d.z + f.z;
        float s3 = a.w + b.w + d.w + f.w;
        if (s0 == 0.f) s0 = 2.2204460492503131e-16f;
        if (s1 == 0.f) s1 = 2.2204460492503131e-16f;
        if (s2 == 0.f) s2 = 2.2204460492503131e-16f;
        if (s3 == 0.f) s3 = 2.2204460492503131e-16f;
        yo[c] = make_float4(__logf(s0), __logf(s1), __logf(s2), __logf(s3));
    }
}

// ---------------------------------------------------------------------------
// Kernel 7: balance loss
// ---------------------------------------------------------------------------
__global__ void loss_kernel(float* __restrict__ out) {
    __shared__ float s_imp[8][EE];
    __shared__ float s_load[8][EE];
    int tid = threadIdx.x, lane = tid & 31, wid = tid >> 5;
    float imp[EE], ld[EE];
#pragma unroll
    for (int e = 0; e < EE; e++) { imp[e] = 0.f; ld[e] = 0.f; }
    for (int b = tid; b < BB; b += 256) {
#pragma unroll
        for (int e = 0; e < EE; e++) {
            float g = g_gates[(size_t)b * EE + e];
            imp[e] += g;
            ld[e]  += (g > 0.f) ? 1.f : 0.f;
        }
    }
#pragma unroll
    for (int off = 16; off; off >>= 1)
#pragma unroll
        for (int e = 0; e < EE; e++) {
            imp[e] += __shfl_xor_sync(0xffffffffu, imp[e], off);
            ld[e]  += __shfl_xor_sync(0xffffffffu, ld[e],  off);
        }
    if (lane == 0)
#pragma unroll
        for (int e = 0; e < EE; e++) { s_imp[wid][e] = imp[e]; s_load[wid][e] = ld[e]; }
    __syncthreads();
    if (tid == 0) {
        float ti[EE], tl[EE];
#pragma unroll
        for (int e = 0; e < EE; e++) { ti[e] = 0.f; tl[e] = 0.f; }
        for (int w = 0; w < 8; w++)
#pragma unroll
            for (int e = 0; e < EE; e++) { ti[e] += s_imp[w][e]; tl[e] += s_load[w][e]; }
        float mi = 0.f, ml = 0.f;
#pragma unroll
        for (int e = 0; e < EE; e++) { mi += ti[e]; ml += tl[e]; }
        mi /= EE; ml /= EE;
        float vi = 0.f, vl = 0.f;
#pragma unroll
        for (int e = 0; e < EE; e++) {
            float di = ti[e] - mi, dl = tl[e] - ml;
            vi += di * di; vl += dl * dl;
        }
        vi /= (EE - 1); vl /= (EE - 1);
        out[(size_t)BB * CC] =
            (vi / (mi * mi + 1e-10f) + vl / (ml * ml + 1e-10f)) * 0.01f;
    }
}

// ---------------------------------------------------------------------------
extern "C" void kernel_launch(void* const* d_in, const int* in_sizes, int n_in,
                              void* d_out, int out_size) {
    const float* x  = (const float*)d_in[0];
    const float* wg = (const float*)d_in[1];
    const float* we = (const float*)d_in[2];
    const float* be = (const float*)d_in[3];
    float* y = (float*)d_out;

    cudaFuncSetAttribute(moe_main, cudaFuncAttributeMaxDynamicSharedMemorySize,
                         SMEM_DYN);

    zero_cnt<<<1, 32>>>();
    gating_kernel<<<BB / 4, 128>>>(x, wg);
    map_kernel<<<1, 32>>>();
    convert_x<<<(BB * DD / 4) / 256, 256>>>(x);
    convert_w<<<(int)(((size_t)EE * DD * CC / 4) / 256), 256>>>(we);

    dim3 grid(MAXT, CC / BN);   // (136, 32)
    moe_main<<<grid, 256, SMEM_DYN>>>(be);

    final_kernel<<<BB, 256>>>(y);
    if (out_size > (long long)BB * CC) loss_kernel<<<1, 256>>>(y);
}

// round 17
// speedup vs baseline: 1.5063x; 1.5063x over previous
#include <cuda_runtime.h>
#include <cuda_fp16.h>
#include <cstdint>

// Problem dims (fixed by the dataset)
#define BB 4096   // batch
#define DD 1024   // model dim
#define EE 8      // experts
#define CC 4096   // expert output dim
#define KSEL 4    // top-k

// Main GEMM tiling
#define BM 128
#define BN 128
#define BK 64
#define NCH 16            // 16 k-chunks; each carries A_h, A_l, B
#define NSTG 2            // double buffer (compute/chunk >> fill latency)
#define ASTR 72           // A smem row stride (elems): 144B -> conflict-free ldmatrix
#define BSTR 136          // B smem row stride (elems): 272B -> conflict-free ldmatrix
#define A_T_B (BM * ASTR * 2)            // 18432 per A tile
#define B_T_B (BK * BSTR * 2)            // 17408 per B tile
#define STAGE_B (2 * A_T_B + B_T_B)      // 54272
#define SMEM_DYN (NSTG * STAGE_B)        // 108544
// offsets within a stage
#define OFF_AH 0
#define OFF_AL A_T_B
#define OFF_B  (2 * A_T_B)
#define MAXT 136                          // max M-tiles

// ---------------------------------------------------------------------------
// Static device scratch (allocation-free rule)
// ---------------------------------------------------------------------------
__device__ float g_gates[BB * EE];
__device__ int   g_cnt[EE];
__device__ int   g_list[EE * BB];          // per-expert row lists (padded with -1)
__device__ int4  g_rowslot[BB];            // per row: 4x ((e<<16)|slot)
__device__ int   g_map_e[MAXT];
__device__ int   g_map_lb[MAXT];           // list-index base for tile
__device__ int   g_pbase[EE];              // padded global slot base per expert
__device__ __align__(16) __half g_x_h[BB * DD];
__device__ __align__(16) __half g_x_l[BB * DD];
__device__ __align__(16) __half g_w[(size_t)EE * DD * CC];
__device__ __align__(16) float g_eo[(size_t)MAXT * BM * CC];  // per-(slot,col) contrib

__device__ __forceinline__ uint32_t smem_u32(const void* p) {
    uint32_t a;
    asm("{ .reg .u64 t; cvta.to.shared.u64 t, %1; cvt.u32.u64 %0, t; }"
        : "=r"(a) : "l"(p));
    return a;
}

// ---------------------------------------------------------------------------
// Kernel 0: zero counters
// ---------------------------------------------------------------------------
__global__ void zero_cnt() { if (threadIdx.x < EE) g_cnt[threadIdx.x] = 0; }

// ---------------------------------------------------------------------------
// Kernel 1: gating. One warp per row; float4 loads for deep MLP.
// ---------------------------------------------------------------------------
__global__ void gating_kernel(const float* __restrict__ x,
                              const float* __restrict__ wg) {
    int row  = (blockIdx.x * blockDim.x + threadIdx.x) >> 5;
    int lane = threadIdx.x & 31;
    if (row >= BB) return;

    const float* xr = x + (size_t)row * DD;
    float acc[EE];
#pragma unroll
    for (int e = 0; e < EE; e++) acc[e] = 0.f;

    // lane handles j = lane*4 + 128*i, 4 consecutive elements via float4
#pragma unroll
    for (int i = 0; i < 8; i++) {
        int j0 = lane * 4 + i * 128;
        float4 xv = *(const float4*)(xr + j0);
        float xq[4] = {xv.x, xv.y, xv.z, xv.w};
#pragma unroll
        for (int q = 0; q < 4; q++) {
            const float4* wr = (const float4*)(wg + (size_t)(j0 + q) * EE);
            float4 w0 = wr[0], w1 = wr[1];
            acc[0] += xq[q] * w0.x; acc[1] += xq[q] * w0.y;
            acc[2] += xq[q] * w0.z; acc[3] += xq[q] * w0.w;
            acc[4] += xq[q] * w1.x; acc[5] += xq[q] * w1.y;
            acc[6] += xq[q] * w1.z; acc[7] += xq[q] * w1.w;
        }
    }
#pragma unroll
    for (int off = 16; off; off >>= 1)
#pragma unroll
        for (int e = 0; e < EE; e++)
            acc[e] += __shfl_xor_sync(0xffffffffu, acc[e], off);

    if (lane == 0) {
        unsigned used = 0;
        float sl[KSEL]; int si[KSEL];
#pragma unroll
        for (int t = 0; t < KSEL; t++) {
            float best = -3.0e38f; int bi = 0;
#pragma unroll
            for (int e = 0; e < EE; e++) {
                bool ok = !((used >> e) & 1u);
                if (ok && acc[e] > best) { best = acc[e]; bi = e; }
            }
            used |= 1u << bi; sl[t] = best; si[t] = bi;
        }
        float m = sl[0], ex[KSEL], s = 0.f;
#pragma unroll
        for (int t = 0; t < KSEL; t++) { ex[t] = expf(sl[t] - m); s += ex[t]; }
        float inv = 1.f / s;
        float out[EE];
#pragma unroll
        for (int e = 0; e < EE; e++) out[e] = 0.f;
#pragma unroll
        for (int t = 0; t < KSEL; t++) out[si[t]] = ex[t] * inv;
#pragma unroll
        for (int e = 0; e < EE; e++) g_gates[(size_t)row * EE + e] = out[e];

        int pk[KSEL];
#pragma unroll
        for (int t = 0; t < KSEL; t++) {
            int slot = atomicAdd(&g_cnt[si[t]], 1);
            g_list[si[t] * BB + slot] = row;
            pk[t] = (si[t] << 16) | slot;
        }
        g_rowslot[row] = make_int4(pk[0], pk[1], pk[2], pk[3]);
    }
}

// ---------------------------------------------------------------------------
// Kernel 2: build tile map (serial, trivial work)
// ---------------------------------------------------------------------------
__global__ void map_kernel() {
    if (threadIdx.x != 0 || blockIdx.x != 0) return;
    int t = 0;
    for (int e = 0; e < EE; e++) {
        int c  = g_cnt[e];
        int nt = (c + BM - 1) >> 7;
        g_pbase[e] = t * BM;
        for (int i = 0; i < nt; i++) {
            g_map_e[t]  = e;
            g_map_lb[t] = e * BB + i * BM;
            t++;
        }
        for (int s = c; s < nt * BM; s++) g_list[e * BB + s] = -1;
    }
    for (; t < MAXT; t++) g_map_e[t] = -1;
}

// ---------------------------------------------------------------------------
// Kernel 3: split x into hi/lo fp16 (x = h + l, ~21-bit effective mantissa)
// ---------------------------------------------------------------------------
__global__ void convert_x(const float* __restrict__ x) {
    int i = blockIdx.x * blockDim.x + threadIdx.x;
    float4 v = ((const float4*)x)[i];
    __half h0 = __float2half(v.x), h1 = __float2half(v.y);
    __half h2 = __float2half(v.z), h3 = __float2half(v.w);
    __half2* hp = (__half2*)g_x_h;
    __half2* lp = (__half2*)g_x_l;
    hp[2 * i]     = __halves2half2(h0, h1);
    hp[2 * i + 1] = __halves2half2(h2, h3);
    lp[2 * i]     = __halves2half2(
        __float2half(v.x - __half2float(h0)),
        __float2half(v.y - __half2float(h1)));
    lp[2 * i + 1] = __halves2half2(
        __float2half(v.z - __half2float(h2)),
        __float2half(v.w - __half2float(h3)));
}

// ---------------------------------------------------------------------------
// Kernel 4: w -> single fp16 copy
// ---------------------------------------------------------------------------
__global__ void convert_w(const float* __restrict__ w) {
    size_t i = (size_t)blockIdx.x * blockDim.x + threadIdx.x;
    float4 v = ((const float4*)w)[i];
    __half2* hp = (__half2*)g_w;
    hp[2 * i]     = __halves2half2(__float2half(v.x), __float2half(v.y));
    hp[2 * i + 1] = __halves2half2(__float2half(v.z), __float2half(v.w));
}

// ---------------------------------------------------------------------------
// Kernel 5: sparse expert GEMM, fp16 two-term split, wide-N, BK=64.
// (Byte-identical to the round-15 852us version.)
// BM=128, BN=128, BK=64. 256 threads, 8 warps as 4(M) x 2(N); warp tile
// 32x64. Per chunk: load A_h, A_l, B once; B fragments held in registers
// across both passes. Double buffer, 1 barrier per (large) chunk, 2 CTAs/SM.
// grid = (MAXT, CC/BN) = (136, 32).
// ---------------------------------------------------------------------------
__global__ __launch_bounds__(256, 2)
void moe_main(const float* __restrict__ be) {
    const int t = blockIdx.x;
    const int e = g_map_e[t];
    if (e < 0) return;
    const int nb = blockIdx.y;

    extern __shared__ __align__(128) char sdyn[];
    __shared__ int   rl[BM];
    __shared__ float Gs[BM];
    __shared__ float Es[BN];

    const int tid   = threadIdx.x;
    const int lane  = tid & 31;
    const int wid   = tid >> 5;
    const int warpM = wid >> 1;          // 0..3 (32 rows each)
    const int warpN = wid & 1;           // 0..1 (64 cols each)

    if (tid < BM) {
        int r = g_list[g_map_lb[t] + tid];
        rl[tid] = (r < 0) ? 0 : r;
        Gs[tid] = (r < 0) ? 0.f : g_gates[(size_t)r * EE + e];
    } else if (tid < BM + BN) {
        Es[tid - BM] = be[(size_t)e * CC + nb * BN + (tid - BM)];
    }
    __syncthreads();

    const uint32_t sb = smem_u32(sdyn);

    // A loader: 128 rows x 64 elems = 1024 x 16B chunks; 4 per thread
    size_t rowoffA[4];
#pragma unroll
    for (int i = 0; i < 4; i++)
        rowoffA[i] = (size_t)rl[(tid + 256 * i) >> 3] * DD + ((tid & 7) * 8);
    uint32_t dstA[4];
#pragma unroll
    for (int i = 0; i < 4; i++)
        dstA[i] = (uint32_t)((((tid + 256 * i) >> 3) * ASTR + (tid & 7) * 8) * 2);
    // B loader: 64 rows x 128 elems = 1024 x 16B chunks; 4 per thread
    const int b_row0 = tid >> 4;             // +16 per i
    const int b_ch   = (tid & 15) * 8;
    uint32_t dstB[4];
#pragma unroll
    for (int i = 0; i < 4; i++)
        dstB[i] = (uint32_t)(((b_row0 + 16 * i) * BSTR + b_ch) * 2);

    const __half* wptr = g_w + (size_t)e * DD * CC;

    auto issue = [&](int kc) {
        int kk = kc * BK;
        uint32_t st = sb + (uint32_t)(kc & 1) * STAGE_B;
#pragma unroll
        for (int i = 0; i < 4; i++) {
            const void* s0 = g_x_h + rowoffA[i] + kk;
            asm volatile("cp.async.cg.shared.global [%0], [%1], 16;"
                         :: "r"(st + OFF_AH + dstA[i]), "l"(s0));
            const void* s1 = g_x_l + rowoffA[i] + kk;
            asm volatile("cp.async.cg.shared.global [%0], [%1], 16;"
                         :: "r"(st + OFF_AL + dstA[i]), "l"(s1));
        }
#pragma unroll
        for (int i = 0; i < 4; i++) {
            const void* s0 = wptr + (size_t)(kk + b_row0 + 16 * i) * CC
                             + nb * BN + b_ch;
            asm volatile("cp.async.cg.shared.global [%0], [%1], 16;"
                         :: "r"(st + OFF_B + dstB[i]), "l"(s0));
        }
        asm volatile("cp.async.commit_group;");
    };

    float acc[2][8][4];
#pragma unroll
    for (int mf = 0; mf < 2; mf++)
#pragma unroll
        for (int nf = 0; nf < 8; nf++)
#pragma unroll
            for (int q = 0; q < 4; q++) acc[mf][nf][q] = 0.f;

    const int lm_row = lane & 15;
    const int lm_col = (lane >> 4) << 3;

    issue(0);

    for (int c = 0; c < NCH; c++) {
        asm volatile("cp.async.wait_group 0;" ::: "memory");
        __syncthreads();
        if (c + 1 < NCH) issue(c + 1);

        uint32_t st = sb + (uint32_t)(c & 1) * STAGE_B;
#pragma unroll
        for (int ks = 0; ks < 4; ks++) {
            uint32_t a[2][4], b[8][2];

            auto loadA = [&](uint32_t ab) {
#pragma unroll
                for (int mf = 0; mf < 2; mf++) {
                    uint32_t addr = ab +
                        (uint32_t)(((warpM * 32 + mf * 16 + lm_row) * ASTR +
                                    ks * 16 + lm_col) * 2);
                    asm volatile(
                        "ldmatrix.sync.aligned.m8n8.x4.shared.b16 {%0,%1,%2,%3}, [%4];"
                        : "=r"(a[mf][0]), "=r"(a[mf][1]),
                          "=r"(a[mf][2]), "=r"(a[mf][3])
                        : "r"(addr));
                }
            };
            auto mma_all = [&]() {
#pragma unroll
                for (int mf = 0; mf < 2; mf++)
#pragma unroll
                    for (int nf = 0; nf < 8; nf++)
                        asm volatile(
                            "mma.sync.aligned.m16n8k16.row.col.f32.f16.f16.f32 "
                            "{%0,%1,%2,%3}, {%4,%5,%6,%7}, {%8,%9}, {%0,%1,%2,%3};"
                            : "+f"(acc[mf][nf][0]), "+f"(acc[mf][nf][1]),
                              "+f"(acc[mf][nf][2]), "+f"(acc[mf][nf][3])
                            : "r"(a[mf][0]), "r"(a[mf][1]),
                              "r"(a[mf][2]), "r"(a[mf][3]),
                              "r"(b[nf][0]), "r"(b[nf][1]));
            };

            // B fragments once per ks, reused across both passes
#pragma unroll
            for (int np = 0; np < 4; np++) {
                uint32_t addr = st + OFF_B +
                    (uint32_t)(((ks * 16 + lm_row) * BSTR +
                                warpN * 64 + np * 16 + lm_col) * 2);
                uint32_t t0, t1, t2, t3;
                asm volatile(
                    "ldmatrix.sync.aligned.m8n8.x4.trans.shared.b16 {%0,%1,%2,%3}, [%4];"
                    : "=r"(t0), "=r"(t1), "=r"(t2), "=r"(t3) : "r"(addr));
                b[np * 2][0] = t0;     b[np * 2][1] = t1;
                b[np * 2 + 1][0] = t2; b[np * 2 + 1][1] = t3;
            }

            loadA(st + OFF_AH);
            mma_all();                     // x_h * w
            loadA(st + OFF_AL);
            mma_all();                     // x_l * w
        }
    }

    // epilogue: g_eo[t*BM + local_row][nb*BN + col] = g * exp(acc + bias)
    const int r0 = warpM * 32 + (lane >> 2);
    const int c0 = warpN * 64 + (lane & 3) * 2;
    float* ob = g_eo + ((size_t)t * BM) * CC + (size_t)nb * BN;
#pragma unroll
    for (int mf = 0; mf < 2; mf++)
#pragma unroll
        for (int q = 0; q < 2; q++) {
            int rr = r0 + mf * 16 + q * 8;
            float g = Gs[rr];
#pragma unroll
            for (int nf = 0; nf < 8; nf++) {
                int cc = c0 + nf * 8;
                float v0 = g * __expf(acc[mf][nf][q * 2 + 0] + Es[cc]);
                float v1 = g * __expf(acc[mf][nf][q * 2 + 1] + Es[cc + 1]);
                *(float2*)(ob + (size_t)rr * CC + cc) = make_float2(v0, v1);
            }
        }
}

// ---------------------------------------------------------------------------
// Kernel 6: final combine. Each block = one row; sum the row's 4 fixed-order
// expert contributions (coalesced streams), eps guard, log.
// ---------------------------------------------------------------------------
__global__ void final_kernel(float* __restrict__ y) {
    int row = blockIdx.x;
    int4 rs = g_rowslot[row];
    const float* p0 = g_eo + (size_t)(g_pbase[rs.x >> 16] + (rs.x & 0xFFFF)) * CC;
    const float* p1 = g_eo + (size_t)(g_pbase[rs.y >> 16] + (rs.y & 0xFFFF)) * CC;
    const float* p2 = g_eo + (size_t)(g_pbase[rs.z >> 16] + (rs.z & 0xFFFF)) * CC;
    const float* p3 = g_eo + (size_t)(g_pbase[rs.w >> 16] + (rs.w & 0xFFFF)) * CC;
    float4* yo = (float4*)(y + (size_t)row * CC);
#pragma unroll
    for (int i = 0; i < 4; i++) {
        int c = threadIdx.x + i * 256;
        float4 a = ((const float4*)p0)[c];
        float4 b = ((const float4*)p1)[c];
        float4 d = ((const float4*)p2)[c];
        float4 f = ((const float4*)p3)[c];
        float s0 = a.x + b.x + d.x + f.x;
        float s1 = a.y + b.y + d.y + f.y;
        float s2 = a.z + b.z + d.z + f.z;
        float s3 = a.w + b.w + d.w + f.w;
        if (s0 == 0.f) s0 = 2.2204460492503131e-16f;
        if (s1 == 0.f) s1 = 2.2204460492503131e-16f;
        if (s2 == 0.f) s2 = 2.2204460492503131e-16f;
        if (s3 == 0.f) s3 = 2.2204460492503131e-16f;
        yo[c] = make_float4(__logf(s0), __logf(s1), __logf(s2), __logf(s3));
    }
}

// ---------------------------------------------------------------------------
// Kernel 7: balance loss
// ---------------------------------------------------------------------------
__global__ void loss_kernel(float* __restrict__ out) {
    __shared__ float s_imp[8][EE];
    __shared__ float s_load[8][EE];
    int tid = threadIdx.x, lane = tid & 31, wid = tid >> 5;
    float imp[EE], ld[EE];
#pragma unroll
    for (int e = 0; e < EE; e++) { imp[e] = 0.f; ld[e] = 0.f; }
    for (int b = tid; b < BB; b += 256) {
#pragma unroll
        for (int e = 0; e < EE; e++) {
            float g = g_gates[(size_t)b * EE + e];
            imp[e] += g;
            ld[e]  += (g > 0.f) ? 1.f : 0.f;
        }
    }
#pragma unroll
    for (int off = 16; off; off >>= 1)
#pragma unroll
        for (int e = 0; e < EE; e++) {
            imp[e] += __shfl_xor_sync(0xffffffffu, imp[e], off);
            ld[e]  += __shfl_xor_sync(0xffffffffu, ld[e],  off);
        }
    if (lane == 0)
#pragma unroll
        for (int e = 0; e < EE; e++) { s_imp[wid][e] = imp[e]; s_load[wid][e] = ld[e]; }
    __syncthreads();
    if (tid == 0) {
        float ti[EE], tl[EE];
#pragma unroll
        for (int e = 0; e < EE; e++) { ti[e] = 0.f; tl[e] = 0.f; }
        for (int w = 0; w < 8; w++)
#pragma unroll
            for (int e = 0; e < EE; e++) { ti[e] += s_imp[w][e]; tl[e] += s_load[w][e]; }
        float mi = 0.f, ml = 0.f;
#pragma unroll
        for (int e = 0; e < EE; e++) { mi += ti[e]; ml += tl[e]; }
        mi /= EE; ml /= EE;
        float vi = 0.f, vl = 0.f;
#pragma unroll
        for (int e = 0; e < EE; e++) {
            float di = ti[e] - mi, dl = tl[e] - ml;
            vi += di * di; vl += dl * dl;
        }
        vi /= (EE - 1); vl /= (EE - 1);
        out[(size_t)BB * CC] =
            (vi / (mi * mi + 1e-10f) + vl / (ml * ml + 1e-10f)) * 0.01f;
    }
}

// ---------------------------------------------------------------------------
extern "C" void kernel_launch(void* const* d_in, const int* in_sizes, int n_in,
                              void* d_out, int out_size) {
    const float* x  = (const float*)d_in[0];
    const float* wg = (const float*)d_in[1];
    const float* we = (const float*)d_in[2];
    const float* be = (const float*)d_in[3];
    float* y = (float*)d_out;

    cudaFuncSetAttribute(moe_main, cudaFuncAttributeMaxDynamicSharedMemorySize,
                         SMEM_DYN);

    zero_cnt<<<1, 32>>>();
    gating_kernel<<<BB / 4, 128>>>(x, wg);
    map_kernel<<<1, 32>>>();
    convert_x<<<(BB * DD / 4) / 256, 256>>>(x);
    convert_w<<<(int)(((size_t)EE * DD * CC / 4) / 256), 256>>>(we);

    dim3 grid(MAXT, CC / BN);   // (136, 32)
    moe_main<<<grid, 256, SMEM_DYN>>>(be);

    final_kernel<<<BB, 256>>>(y);
    if (out_size > (long long)BB * CC) loss_kernel<<<1, 256>>>(y);
}